// round 9
// baseline (speedup 1.0000x reference)
#include <cuda_runtime.h>
#include <math.h>
#include <stdint.h>

#define N_TOK 4096      // B*S
#define DDIM  1024      // D
#define FDIM  4096      // F
#define NEXP  8         // E
#define LN_EPS 1e-5f

#define BM 128
#define BN 128
#define BK 128                   // int8 elements per chunk = 128 B rows
#define ROWB 144                 // 128 B data + 16 B pad per smem row
#define ATILE (128 * ROWB)       // 18432 B per operand tile
#define BUFSZ (4 * ATILE)        // A1, A0, B1, B0
#define SMEM_BYTES (2 * BUFSZ)   // 147456 B double buffered

// ---- static device scratch (no runtime allocation allowed) ----
__device__ int   g_counts[NEXP];
__device__ int   g_rows[NEXP * N_TOK];          // value = token*2 + slot
__device__ float g_slotw[2 * N_TOK];            // softmax weight per slot
// int8 split-2 operands + per-row scales
__device__ float g_sX[N_TOK];
__device__ char  g_Xq1[N_TOK * DDIM];
__device__ char  g_Xq0[N_TOK * DDIM];
__device__ float g_sW1[NEXP * FDIM];
__device__ char  g_W1q1[NEXP * FDIM * DDIM];
__device__ char  g_W1q0[NEXP * FDIM * DDIM];
__device__ float g_sW2[NEXP * DDIM];
__device__ char  g_W2q1[NEXP * DDIM * FDIM];
__device__ char  g_W2q0[NEXP * DDIM * FDIM];
// intermediate H (fp32) + its quantized form
__device__ float g_Hf[(size_t)2 * N_TOK * FDIM];
__device__ float g_sH[2 * N_TOK];
__device__ char  g_Hq1[(size_t)2 * N_TOK * FDIM];
__device__ char  g_Hq0[(size_t)2 * N_TOK * FDIM];
__device__ float g_Y[(size_t)2 * N_TOK * DDIM]; // H@W2^T+b2 (unweighted)

// ============================ PTX helpers ============================
static __device__ __forceinline__ void cp16(uint32_t s, const void* g) {
    asm volatile("cp.async.cg.shared.global [%0], [%1], 16;" :: "r"(s), "l"(g));
}

#define LDSM4(r0, r1, r2, r3, addr)                                           \
    asm volatile("ldmatrix.sync.aligned.m8n8.x4.shared.b16 {%0,%1,%2,%3}, [%4];" \
                 : "=r"(r0), "=r"(r1), "=r"(r2), "=r"(r3) : "r"(addr))

#define MMAI8(d, a, b0, b1)                                                   \
    asm volatile("mma.sync.aligned.m16n8k32.row.col.s32.s8.s8.s32 "           \
                 "{%0,%1,%2,%3}, {%4,%5,%6,%7}, {%8,%9}, {%0,%1,%2,%3};"      \
                 : "+r"((d)[0]), "+r"((d)[1]), "+r"((d)[2]), "+r"((d)[3])     \
                 : "r"((a)[0]), "r"((a)[1]), "r"((a)[2]), "r"((a)[3]),        \
                   "r"(b0), "r"(b1))

// ============================ small kernels ============================
__global__ void init_counts_kernel() {
    if (threadIdx.x < NEXP) g_counts[threadIdx.x] = 0;
}

// per-row amax + int8 split-2 quantization: a ~= s*(q1 + q0/254), s = amax/127
__global__ void quant_rows_kernel(const float* __restrict__ src,
                                  char* __restrict__ q1,
                                  char* __restrict__ q0,
                                  float* __restrict__ scale, int K) {
    int row = blockIdx.x;
    const float* p = src + (size_t)row * K;
    int tid = threadIdx.x;
    __shared__ float sred[8];

    float amax = 0.f;
    for (int i = tid * 4; i < K; i += 1024) {
        float4 v = *(const float4*)(p + i);
        amax = fmaxf(amax, fmaxf(fmaxf(fabsf(v.x), fabsf(v.y)),
                                 fmaxf(fabsf(v.z), fabsf(v.w))));
    }
#pragma unroll
    for (int o = 16; o > 0; o >>= 1)
        amax = fmaxf(amax, __shfl_xor_sync(0xffffffffu, amax, o));
    if ((tid & 31) == 0) sred[tid >> 5] = amax;
    __syncthreads();
    amax = fmaxf(fmaxf(fmaxf(sred[0], sred[1]), fmaxf(sred[2], sred[3])),
                 fmaxf(fmaxf(sred[4], sred[5]), fmaxf(sred[6], sred[7])));
    if (amax < 1e-30f) amax = 1e-30f;
    float s    = amax * (1.f / 127.f);
    float inv1 = 127.f / amax;
    float inv2 = 254.f / s;
    if (tid == 0) scale[row] = s;

    for (int i = tid * 4; i < K; i += 1024) {
        float4 v = *(const float4*)(p + i);
        float vv[4] = {v.x, v.y, v.z, v.w};
        char c1[4], c0[4];
#pragma unroll
        for (int j = 0; j < 4; j++) {
            float a1 = rintf(vv[j] * inv1);
            a1 = fminf(fmaxf(a1, -127.f), 127.f);
            float r  = vv[j] - a1 * s;
            float a0 = rintf(r * inv2);
            a0 = fminf(fmaxf(a0, -127.f), 127.f);
            c1[j] = (char)(int)a1;
            c0[j] = (char)(int)a0;
        }
        *(char4*)(q1 + (size_t)row * K + i) = make_char4(c1[0], c1[1], c1[2], c1[3]);
        *(char4*)(q0 + (size_t)row * K + i) = make_char4(c0[0], c0[1], c0[2], c0[3]);
    }
}

// One warp per token: 8 logits, top-2, softmax, append to expert lists.
__global__ void router_kernel(const float* __restrict__ tgt,
                              const float* __restrict__ Wr,
                              const float* __restrict__ br) {
    int token = blockIdx.x * 8 + (threadIdx.x >> 5);
    int lane  = threadIdx.x & 31;
    if (token >= N_TOK) return;

    const float* x = tgt + (size_t)token * DDIM;
    float xr[32];
#pragma unroll
    for (int i = 0; i < 32; i++) xr[i] = x[lane + 32 * i];

    float logits[NEXP];
#pragma unroll
    for (int e = 0; e < NEXP; e++) {
        const float* w = Wr + e * DDIM;
        float s = 0.f;
#pragma unroll
        for (int i = 0; i < 32; i++) s += xr[i] * w[lane + 32 * i];
#pragma unroll
        for (int o = 16; o > 0; o >>= 1) s += __shfl_xor_sync(0xffffffffu, s, o);
        logits[e] = s + br[e];
    }

    if (lane == 0) {
        int i0 = 0; float v0 = logits[0];
#pragma unroll
        for (int e = 1; e < NEXP; e++) if (logits[e] > v0) { v0 = logits[e]; i0 = e; }
        int i1 = -1; float v1 = -INFINITY;
#pragma unroll
        for (int e = 0; e < NEXP; e++) if (e != i0 && logits[e] > v1) { v1 = logits[e]; i1 = e; }
        float e1  = expf(v1 - v0);
        float inv = 1.f / (1.f + e1);
        g_slotw[2 * token]     = inv;
        g_slotw[2 * token + 1] = e1 * inv;
        int p0 = atomicAdd(&g_counts[i0], 1); g_rows[i0 * N_TOK + p0] = 2 * token;
        int p1 = atomicAdd(&g_counts[i1], 1); g_rows[i1 * N_TOK + p1] = 2 * token + 1;
    }
}

// ============================ int8 mma grouped GEMM ============================
// C[m][n] = s_a[m]*s_b[n]*( sum a1*b1 + (sum a1*b0 + a0*b1)/254 ) + bias
// 256 thr = 8 warps (2 M x 4 N), warp tile 64x32, block tile 128x128, BK=128 int8.
__global__ void __launch_bounds__(256, 1)
imma_gemm_kernel(int is_gemm1, int Ndim, int Kdim,
                 const char* __restrict__ Aq1, const char* __restrict__ Aq0,
                 const float* __restrict__ As,
                 const char* __restrict__ Bq1, const char* __restrict__ Bq0,
                 const float* __restrict__ Bs,
                 const float* __restrict__ bias) {
    extern __shared__ __align__(128) char smem[];
    uint32_t sb = (uint32_t)__cvta_generic_to_shared(smem);

    int e  = blockIdx.z;
    int nt = blockIdx.y;
    int mt = blockIdx.x;   // mt fastest -> concurrent blocks share weight tiles in L2
    int cnt = g_counts[e];
    if (mt * BM >= cnt) return;

    const int* erows = g_rows + e * N_TOK;
    int tid = threadIdx.x;

    // ---- global->smem geometry: thread -> (row = tid>>1, 64B half = tid&1) ----
    int lrow = tid >> 1;
    int half = tid & 1;
    int mr_l = mt * BM + lrow; if (mr_l > cnt - 1) mr_l = cnt - 1;
    int arow = erows[mr_l]; if (is_gemm1) arow >>= 1;
    const char* ap1 = Aq1 + (size_t)arow * Kdim + half * 64;
    const char* ap0 = Aq0 + (size_t)arow * Kdim + half * 64;
    size_t wo = ((size_t)e * Ndim + nt * BN + lrow) * Kdim + half * 64;
    const char* bp1 = Bq1 + wo;
    const char* bp0 = Bq0 + wo;
    uint32_t dstoff = (uint32_t)lrow * ROWB + half * 64;

    // ---- fragment (ldmatrix) geometry ----
    int lane = tid & 31, wid = tid >> 5;
    int wm = wid & 1, wn = wid >> 1;        // warp tile origin (wm*64, wn*32)
    uint32_t afa = (uint32_t)(wm * 64 + (lane & 15)) * ROWB + (lane >> 4) * 16;
    uint32_t bfa = (uint32_t)(wn * 32 + (lane & 15)) * ROWB + (lane >> 4) * 16;

    int accM[4][4][4], accC[4][4][4];
#pragma unroll
    for (int mi = 0; mi < 4; mi++)
#pragma unroll
        for (int ni = 0; ni < 4; ni++)
#pragma unroll
            for (int r = 0; r < 4; r++) { accM[mi][ni][r] = 0; accC[mi][ni][r] = 0; }

    auto issue = [&](int i, int b) {
        uint32_t d = sb + (uint32_t)b * BUFSZ + dstoff;
        size_t ko = (size_t)i * BK;
#pragma unroll
        for (int j = 0; j < 4; j++) {
            cp16(d + j * 16,              ap1 + ko + j * 16);
            cp16(d + ATILE + j * 16,      ap0 + ko + j * 16);
            cp16(d + 2 * ATILE + j * 16,  bp1 + ko + j * 16);
            cp16(d + 3 * ATILE + j * 16,  bp0 + ko + j * 16);
        }
        asm volatile("cp.async.commit_group;" ::: "memory");
    };

    int nch = Kdim / BK;
    issue(0, 0);
    for (int i = 0; i < nch; i++) {
        if (i + 1 < nch) {
            issue(i + 1, (i + 1) & 1);
            asm volatile("cp.async.wait_group 1;" ::: "memory");
        } else {
            asm volatile("cp.async.wait_group 0;" ::: "memory");
        }
        __syncthreads();

        uint32_t bb = sb + (uint32_t)(i & 1) * BUFSZ;
#pragma unroll
        for (int s = 0; s < 4; s++) {       // four k32 steps per 128B chunk
            uint32_t aA = bb + afa + s * 32;
            uint32_t aB = bb + 2 * ATILE + bfa + s * 32;
            uint32_t af[4][4], b1f[2][4], b0f[2][4];

            // A1 fragments (4) + B1 fragments (2)
#pragma unroll
            for (int mi = 0; mi < 4; mi++)
                LDSM4(af[mi][0], af[mi][1], af[mi][2], af[mi][3], aA + mi * 16 * ROWB);
#pragma unroll
            for (int nj = 0; nj < 2; nj++)
                LDSM4(b1f[nj][0], b1f[nj][1], b1f[nj][2], b1f[nj][3], aB + nj * 16 * ROWB);

            // main: a1*b1
#pragma unroll
            for (int mi = 0; mi < 4; mi++)
#pragma unroll
                for (int ni = 0; ni < 4; ni++)
                    MMAI8(accM[mi][ni], af[mi],
                          b1f[ni >> 1][ni & 1], b1f[ni >> 1][(ni & 1) + 2]);

            // B0 fragments (2)
#pragma unroll
            for (int nj = 0; nj < 2; nj++)
                LDSM4(b0f[nj][0], b0f[nj][1], b0f[nj][2], b0f[nj][3],
                      aB + ATILE + nj * 16 * ROWB);

            // cross: a1*b0
#pragma unroll
            for (int mi = 0; mi < 4; mi++)
#pragma unroll
                for (int ni = 0; ni < 4; ni++)
                    MMAI8(accC[mi][ni], af[mi],
                          b0f[ni >> 1][ni & 1], b0f[ni >> 1][(ni & 1) + 2]);

            // A0 fragments overwrite A1 slots (4)
#pragma unroll
            for (int mi = 0; mi < 4; mi++)
                LDSM4(af[mi][0], af[mi][1], af[mi][2], af[mi][3],
                      aA + ATILE + mi * 16 * ROWB);

            // cross: a0*b1
#pragma unroll
            for (int mi = 0; mi < 4; mi++)
#pragma unroll
                for (int ni = 0; ni < 4; ni++)
                    MMAI8(accC[mi][ni], af[mi],
                          b1f[ni >> 1][ni & 1], b1f[ni >> 1][(ni & 1) + 2]);
        }
        __syncthreads();
    }

    // ---- epilogue ----
    int tg = lane >> 2, tc = (lane & 3) * 2;
    const float* bbias = bias + e * Ndim + nt * BN;
    const float* bsc   = Bs + e * Ndim + nt * BN;
    float bias_r[8], sbv[8];
#pragma unroll
    for (int ni = 0; ni < 4; ni++) {
        int c = wn * 32 + ni * 8 + tc;
        bias_r[2 * ni]     = __ldg(bbias + c);
        bias_r[2 * ni + 1] = __ldg(bbias + c + 1);
        sbv[2 * ni]        = __ldg(bsc + c);
        sbv[2 * ni + 1]    = __ldg(bsc + c + 1);
    }
#pragma unroll
    for (int mi = 0; mi < 4; mi++) {
#pragma unroll
        for (int hh = 0; hh < 2; hh++) {
            int r = wm * 64 + mi * 16 + tg + hh * 8;
            int mr = mt * BM + r;
            if (mr < cnt) {
                int orow = erows[mr];
                float sa = is_gemm1 ? __ldg(As + (orow >> 1)) : __ldg(As + orow);
#pragma unroll
                for (int ni = 0; ni < 4; ni++) {
                    int c = wn * 32 + ni * 8 + tc;
                    float f0 = (float)accM[mi][ni][hh * 2]
                             + (float)accC[mi][ni][hh * 2] * (1.f / 254.f);
                    float f1 = (float)accM[mi][ni][hh * 2 + 1]
                             + (float)accC[mi][ni][hh * 2 + 1] * (1.f / 254.f);
                    float v0 = f0 * (sa * sbv[2 * ni])     + bias_r[2 * ni];
                    float v1 = f1 * (sa * sbv[2 * ni + 1]) + bias_r[2 * ni + 1];
                    int n = nt * BN + c;
                    if (is_gemm1) {
                        float2 t; t.x = fmaxf(v0, 0.f); t.y = fmaxf(v1, 0.f);
                        *(float2*)(g_Hf + (size_t)orow * FDIM + n) = t;
                    } else {
                        float2 t; t.x = v0; t.y = v1;
                        *(float2*)(g_Y + (size_t)orow * DDIM + n) = t;
                    }
                }
            }
        }
    }
}

// ============================ LN ============================
__global__ void ln_kernel(const float* __restrict__ tgt,
                          const float* __restrict__ gamma,
                          const float* __restrict__ beta,
                          float* __restrict__ out) {
    int token = blockIdx.x;
    int tid = threadIdx.x;
    __shared__ float red[8];

    float w0 = g_slotw[2 * token], w1 = g_slotw[2 * token + 1];
    const float* x  = tgt + (size_t)token * DDIM;
    const float* y0 = g_Y + (size_t)(2 * token) * DDIM;
    const float* y1 = y0 + DDIM;

    float v[4];
    float s = 0.f;
#pragma unroll
    for (int i = 0; i < 4; i++) {
        int d = tid + 256 * i;
        v[i] = x[d] + w0 * y0[d] + w1 * y1[d];
        s += v[i];
    }
#pragma unroll
    for (int o = 16; o > 0; o >>= 1) s += __shfl_xor_sync(0xffffffffu, s, o);
    if ((tid & 31) == 0) red[tid >> 5] = s;
    __syncthreads();
    float mu = (red[0] + red[1] + red[2] + red[3] + red[4] + red[5] + red[6] + red[7]) * (1.f / DDIM);

    float sq = 0.f;
#pragma unroll
    for (int i = 0; i < 4; i++) { float dv = v[i] - mu; sq += dv * dv; }
#pragma unroll
    for (int o = 16; o > 0; o >>= 1) sq += __shfl_xor_sync(0xffffffffu, sq, o);
    __syncthreads();
    if ((tid & 31) == 0) red[tid >> 5] = sq;
    __syncthreads();
    float var = (red[0] + red[1] + red[2] + red[3] + red[4] + red[5] + red[6] + red[7]) * (1.f / DDIM);
    float inv = rsqrtf(var + LN_EPS);

#pragma unroll
    for (int i = 0; i < 4; i++) {
        int d = tid + 256 * i;
        out[(size_t)token * DDIM + d] = (v[i] - mu) * inv * gamma[d] + beta[d];
    }
}

// ============================ launch ============================
extern "C" void kernel_launch(void* const* d_in, const int* in_sizes, int n_in,
                              void* d_out, int out_size) {
    const float* tgt   = (const float*)d_in[0];
    const float* Wr    = (const float*)d_in[1];
    const float* br    = (const float*)d_in[2];
    const float* W1    = (const float*)d_in[3];
    const float* b1    = (const float*)d_in[4];
    const float* W2    = (const float*)d_in[5];
    const float* b2    = (const float*)d_in[6];
    const float* gamma = (const float*)d_in[7];
    const float* beta  = (const float*)d_in[8];
    float* out = (float*)d_out;

    cudaFuncSetAttribute(imma_gemm_kernel,
                         cudaFuncAttributeMaxDynamicSharedMemorySize, SMEM_BYTES);

    // resolve scratch symbols
    char *xq1, *xq0, *w1q1, *w1q0, *w2q1, *w2q0, *hq1, *hq0;
    float *sx, *sw1, *sw2, *sh, *hf;
    cudaGetSymbolAddress((void**)&xq1,  g_Xq1);
    cudaGetSymbolAddress((void**)&xq0,  g_Xq0);
    cudaGetSymbolAddress((void**)&sx,   g_sX);
    cudaGetSymbolAddress((void**)&w1q1, g_W1q1);
    cudaGetSymbolAddress((void**)&w1q0, g_W1q0);
    cudaGetSymbolAddress((void**)&sw1,  g_sW1);
    cudaGetSymbolAddress((void**)&w2q1, g_W2q1);
    cudaGetSymbolAddress((void**)&w2q0, g_W2q0);
    cudaGetSymbolAddress((void**)&sw2,  g_sW2);
    cudaGetSymbolAddress((void**)&hq1,  g_Hq1);
    cudaGetSymbolAddress((void**)&hq0,  g_Hq0);
    cudaGetSymbolAddress((void**)&sh,   g_sH);
    cudaGetSymbolAddress((void**)&hf,   g_Hf);

    init_counts_kernel<<<1, 32>>>();
    router_kernel<<<N_TOK / 8, 256>>>(tgt, Wr, br);

    // int8 split-2 quantization (per row)
    quant_rows_kernel<<<N_TOK, 256>>>(tgt, xq1, xq0, sx, DDIM);
    quant_rows_kernel<<<NEXP * FDIM, 256>>>(W1, w1q1, w1q0, sw1, DDIM);
    quant_rows_kernel<<<NEXP * DDIM, 256>>>(W2, w2q1, w2q0, sw2, FDIM);

    // GEMM1: X(int8 split) @ W1^T -> Hf fp32 (bias+relu)
    dim3 g1(N_TOK / BM, FDIM / BN, NEXP);   // x=mt, y=nt, z=e
    imma_gemm_kernel<<<g1, 256, SMEM_BYTES>>>(1, FDIM, DDIM,
                                              xq1, xq0, sx, w1q1, w1q0, sw1, b1);

    // quantize H rows
    quant_rows_kernel<<<2 * N_TOK, 256>>>(hf, hq1, hq0, sh, FDIM);

    // GEMM2: H(int8 split) @ W2^T -> Y fp32 (bias)
    dim3 g2(N_TOK / BM, DDIM / BN, NEXP);
    imma_gemm_kernel<<<g2, 256, SMEM_BYTES>>>(0, DDIM, FDIM,
                                              hq1, hq0, sh, w2q1, w2q0, sw2, b2);

    ln_kernel<<<N_TOK, 256>>>(tgt, gamma, beta, out);
}

// round 10
// speedup vs baseline: 2.2022x; 2.2022x over previous
#include <cuda_runtime.h>
#include <cuda_bf16.h>
#include <math.h>
#include <stdint.h>

#define N_TOK 4096      // B*S
#define DDIM  1024      // D
#define FDIM  4096      // F
#define NEXP  8         // E
#define LN_EPS 1e-5f

#define BM 128
#define BN 128
#define BK 32
#define ROWB 80                  // smem bytes per row: 32 bf16 + 8 pad
#define ATILE (128 * ROWB)       // 10240 B per operand tile
#define STAGEB (4 * ATILE)       // Ah, Al, Bh, Bl = 40960 B per stage
#define NSTAGE 3
#define SMEM_BYTES (NSTAGE * STAGEB)  // 122880 B

// ---- static device scratch (no runtime allocation allowed) ----
__device__ int   g_counts[NEXP];
__device__ int   g_rows[NEXP * N_TOK];          // value = token*2 + slot
__device__ float g_slotw[2 * N_TOK];            // softmax weight per slot
__device__ __nv_bfloat16 g_Xhi[N_TOK * DDIM];
__device__ __nv_bfloat16 g_Xlo[N_TOK * DDIM];
__device__ __nv_bfloat16 g_W1hi[NEXP * FDIM * DDIM];
__device__ __nv_bfloat16 g_W1lo[NEXP * FDIM * DDIM];
__device__ __nv_bfloat16 g_W2hi[NEXP * DDIM * FDIM];
__device__ __nv_bfloat16 g_W2lo[NEXP * DDIM * FDIM];
__device__ __nv_bfloat16 g_Hhi[(size_t)2 * N_TOK * FDIM];
__device__ __nv_bfloat16 g_Hlo[(size_t)2 * N_TOK * FDIM];
__device__ float g_Y[(size_t)2 * N_TOK * DDIM]; // [8192][1024] H@W2^T+b2 (unweighted)

// ============================ PTX helpers ============================
static __device__ __forceinline__ void cp16(uint32_t s, const void* g) {
    asm volatile("cp.async.cg.shared.global [%0], [%1], 16;" :: "r"(s), "l"(g));
}

#define LDSM4(r0, r1, r2, r3, addr)                                           \
    asm volatile("ldmatrix.sync.aligned.m8n8.x4.shared.b16 {%0,%1,%2,%3}, [%4];" \
                 : "=r"(r0), "=r"(r1), "=r"(r2), "=r"(r3) : "r"(addr))

#define MMA16816(d, a, b0, b1)                                                \
    asm volatile("mma.sync.aligned.m16n8k16.row.col.f32.bf16.bf16.f32 "       \
                 "{%0,%1,%2,%3}, {%4,%5,%6,%7}, {%8,%9}, {%0,%1,%2,%3};"      \
                 : "+f"((d)[0]), "+f"((d)[1]), "+f"((d)[2]), "+f"((d)[3])     \
                 : "r"((a)[0]), "r"((a)[1]), "r"((a)[2]), "r"((a)[3]),        \
                   "r"(b0), "r"(b1))

// ============================ small kernels ============================
__global__ void init_counts_kernel() {
    if (threadIdx.x < NEXP) g_counts[threadIdx.x] = 0;
}

// fp32 -> bf16 hi/lo split
__global__ void split_bf16_kernel(const float* __restrict__ src,
                                  __nv_bfloat16* __restrict__ hi,
                                  __nv_bfloat16* __restrict__ lo, int n) {
    int i = (blockIdx.x * blockDim.x + threadIdx.x) * 4;
    if (i >= n) return;
    float4 v = *(const float4*)(src + i);
    float vv[4] = {v.x, v.y, v.z, v.w};
    __nv_bfloat16 h[4], l[4];
#pragma unroll
    for (int j = 0; j < 4; j++) {
        h[j] = __float2bfloat16(vv[j]);
        l[j] = __float2bfloat16(vv[j] - __bfloat162float(h[j]));
    }
    __nv_bfloat162 h0; h0.x = h[0]; h0.y = h[1];
    __nv_bfloat162 h1; h1.x = h[2]; h1.y = h[3];
    __nv_bfloat162 l0; l0.x = l[0]; l0.y = l[1];
    __nv_bfloat162 l1; l1.x = l[2]; l1.y = l[3];
    *(__nv_bfloat162*)(hi + i)     = h0;
    *(__nv_bfloat162*)(hi + i + 2) = h1;
    *(__nv_bfloat162*)(lo + i)     = l0;
    *(__nv_bfloat162*)(lo + i + 2) = l1;
}

// One warp per token: 8 logits, top-2, softmax, append to expert lists.
__global__ void router_kernel(const float* __restrict__ tgt,
                              const float* __restrict__ Wr,
                              const float* __restrict__ br) {
    int token = blockIdx.x * 8 + (threadIdx.x >> 5);
    int lane  = threadIdx.x & 31;
    if (token >= N_TOK) return;

    const float* x = tgt + (size_t)token * DDIM;
    float xr[32];
#pragma unroll
    for (int i = 0; i < 32; i++) xr[i] = x[lane + 32 * i];

    float logits[NEXP];
#pragma unroll
    for (int e = 0; e < NEXP; e++) {
        const float* w = Wr + e * DDIM;
        float s = 0.f;
#pragma unroll
        for (int i = 0; i < 32; i++) s += xr[i] * w[lane + 32 * i];
#pragma unroll
        for (int o = 16; o > 0; o >>= 1) s += __shfl_xor_sync(0xffffffffu, s, o);
        logits[e] = s + br[e];
    }

    if (lane == 0) {
        int i0 = 0; float v0 = logits[0];
#pragma unroll
        for (int e = 1; e < NEXP; e++) if (logits[e] > v0) { v0 = logits[e]; i0 = e; }
        int i1 = -1; float v1 = -INFINITY;
#pragma unroll
        for (int e = 0; e < NEXP; e++) if (e != i0 && logits[e] > v1) { v1 = logits[e]; i1 = e; }
        float e1  = expf(v1 - v0);
        float inv = 1.f / (1.f + e1);
        g_slotw[2 * token]     = inv;
        g_slotw[2 * token + 1] = e1 * inv;
        int p0 = atomicAdd(&g_counts[i0], 1); g_rows[i0 * N_TOK + p0] = 2 * token;
        int p1 = atomicAdd(&g_counts[i1], 1); g_rows[i1 * N_TOK + p1] = 2 * token + 1;
    }
}

// ============================ mma.sync grouped GEMM ============================
// C[m][n] = sum_k A[m][k]*B[n][k], A/B each split bf16 hi+lo:
//   D += Ah*Bh + Ah*Bl + Al*Bh  (fp32 register accumulate)
// 512 thr = 16 warps (4 M x 4 N), warp tile 32x32, block tile 128x128, BK=32.
// 3-stage cp.async ring, ONE __syncthreads per K-chunk.
__global__ void __launch_bounds__(512, 1)
mma_gemm_kernel(int is_gemm1, int Ndim, int Kdim, const float* __restrict__ bias) {
    extern __shared__ __align__(128) char smem[];
    uint32_t sb = (uint32_t)__cvta_generic_to_shared(smem);

    int e  = blockIdx.z;
    int nt = blockIdx.y;
    int mt = blockIdx.x;     // mt fastest -> concurrent blocks share weight tile (L2)
    int cnt = g_counts[e];
    if (mt * BM >= cnt) return;

    const int* erows = g_rows + e * N_TOK;
    const __nv_bfloat16 *Ahb, *Alb, *Whb, *Wlb;
    if (is_gemm1) { Ahb = g_Xhi; Alb = g_Xlo; Whb = g_W1hi; Wlb = g_W1lo; }
    else          { Ahb = g_Hhi; Alb = g_Hlo; Whb = g_W2hi; Wlb = g_W2lo; }

    int tid = threadIdx.x;

    // ---- global->smem geometry: thread -> (row = tid>>2, 16B seg = tid&3) ----
    int lrow = tid >> 2;
    int seg  = tid & 3;
    int kb   = seg * 8;                      // element offset of this thread's 16B
    int mr_l = mt * BM + lrow; if (mr_l > cnt - 1) mr_l = cnt - 1;
    int arow = erows[mr_l]; if (is_gemm1) arow >>= 1;
    const __nv_bfloat16* aph = Ahb + (size_t)arow * Kdim + kb;
    const __nv_bfloat16* apl = Alb + (size_t)arow * Kdim + kb;
    size_t wo = ((size_t)e * Ndim + nt * BN + lrow) * Kdim + kb;
    const __nv_bfloat16* bph = Whb + wo;
    const __nv_bfloat16* bpl = Wlb + wo;
    uint32_t dst = (uint32_t)lrow * ROWB + seg * 16;

    // ---- fragment (ldmatrix) geometry ----
    int lane = tid & 31, wid = tid >> 5;
    int wm = wid & 3, wn = wid >> 2;         // warp tile origin (wm*32, wn*32)
    uint32_t afa = (uint32_t)(wm * 32 + (lane & 15)) * ROWB + (lane >> 4) * 16;
    uint32_t bfa = (uint32_t)(wn * 32 + (lane & 15)) * ROWB + (lane >> 4) * 16;

    float acc[2][4][4];
#pragma unroll
    for (int mi = 0; mi < 2; mi++)
#pragma unroll
        for (int ni = 0; ni < 4; ni++)
#pragma unroll
            for (int r = 0; r < 4; r++) acc[mi][ni][r] = 0.f;

    auto issue = [&](int i) {
        uint32_t d = sb + (uint32_t)(i % NSTAGE) * STAGEB + dst;
        size_t ko = (size_t)i * BK;
        cp16(d,              aph + ko);
        cp16(d + ATILE,      apl + ko);
        cp16(d + 2 * ATILE,  bph + ko);
        cp16(d + 3 * ATILE,  bpl + ko);
        asm volatile("cp.async.commit_group;" ::: "memory");
    };

    int nch = Kdim / BK;
    issue(0);
    if (nch > 1) issue(1);
    for (int i = 0; i < nch; i++) {
        // wait chunk i complete: outstanding groups beyond i = 1 normally, 0 at tail
        if (i + 1 < nch) {
            asm volatile("cp.async.wait_group 1;" ::: "memory");
        } else {
            asm volatile("cp.async.wait_group 0;" ::: "memory");
        }
        __syncthreads();   // chunk i visible to all; stage (i+2)%3 free for reuse
        if (i + 2 < nch) issue(i + 2);

        uint32_t bb = sb + (uint32_t)(i % NSTAGE) * STAGEB;
#pragma unroll
        for (int s = 0; s < 2; s++) {        // two k16 steps per chunk
            uint32_t aA = bb + afa + s * 32;           // Ah (then Al)
            uint32_t aB = bb + 2 * ATILE + bfa + s * 32; // Bh
            uint32_t af[2][4], bhf[2][4], blf[2][4];

            // Ah fragments (2) + Bh fragments (2)
#pragma unroll
            for (int mi = 0; mi < 2; mi++)
                LDSM4(af[mi][0], af[mi][1], af[mi][2], af[mi][3], aA + mi * 16 * ROWB);
#pragma unroll
            for (int nj = 0; nj < 2; nj++)
                LDSM4(bhf[nj][0], bhf[nj][1], bhf[nj][2], bhf[nj][3], aB + nj * 16 * ROWB);

            // p0: Ah * Bh
#pragma unroll
            for (int mi = 0; mi < 2; mi++)
#pragma unroll
                for (int ni = 0; ni < 4; ni++)
                    MMA16816(acc[mi][ni], af[mi],
                             bhf[ni >> 1][ni & 1], bhf[ni >> 1][(ni & 1) + 2]);

            // Bl fragments (2)
#pragma unroll
            for (int nj = 0; nj < 2; nj++)
                LDSM4(blf[nj][0], blf[nj][1], blf[nj][2], blf[nj][3],
                      aB + ATILE + nj * 16 * ROWB);

            // p1: Ah * Bl
#pragma unroll
            for (int mi = 0; mi < 2; mi++)
#pragma unroll
                for (int ni = 0; ni < 4; ni++)
                    MMA16816(acc[mi][ni], af[mi],
                             blf[ni >> 1][ni & 1], blf[ni >> 1][(ni & 1) + 2]);

            // Al fragments overwrite Ah slots (2)
#pragma unroll
            for (int mi = 0; mi < 2; mi++)
                LDSM4(af[mi][0], af[mi][1], af[mi][2], af[mi][3],
                      aA + ATILE + mi * 16 * ROWB);

            // p2: Al * Bh
#pragma unroll
            for (int mi = 0; mi < 2; mi++)
#pragma unroll
                for (int ni = 0; ni < 4; ni++)
                    MMA16816(acc[mi][ni], af[mi],
                             bhf[ni >> 1][ni & 1], bhf[ni >> 1][(ni & 1) + 2]);
        }
    }

    // ---- epilogue ----
    int tg = lane >> 2, tc = (lane & 3) * 2;
    const float* bbias = bias + e * Ndim + nt * BN;
    float bias_r[8];
#pragma unroll
    for (int ni = 0; ni < 4; ni++) {
        int c = wn * 32 + ni * 8 + tc;
        bias_r[2 * ni]     = __ldg(bbias + c);
        bias_r[2 * ni + 1] = __ldg(bbias + c + 1);
    }
#pragma unroll
    for (int mi = 0; mi < 2; mi++) {
#pragma unroll
        for (int half = 0; half < 2; half++) {
            int r = wm * 32 + mi * 16 + tg + half * 8;
            int mr = mt * BM + r;
            if (mr < cnt) {
                int orow = erows[mr];
#pragma unroll
                for (int ni = 0; ni < 4; ni++) {
                    int c = wn * 32 + ni * 8 + tc;
                    float v0 = acc[mi][ni][half * 2]     + bias_r[2 * ni];
                    float v1 = acc[mi][ni][half * 2 + 1] + bias_r[2 * ni + 1];
                    int n = nt * BN + c;
                    if (is_gemm1) {
                        v0 = fmaxf(v0, 0.f); v1 = fmaxf(v1, 0.f);
                        __nv_bfloat16 h0 = __float2bfloat16(v0);
                        __nv_bfloat16 h1 = __float2bfloat16(v1);
                        __nv_bfloat162 hh; hh.x = h0; hh.y = h1;
                        __nv_bfloat162 ll;
                        ll.x = __float2bfloat16(v0 - __bfloat162float(h0));
                        ll.y = __float2bfloat16(v1 - __bfloat162float(h1));
                        *(__nv_bfloat162*)(g_Hhi + (size_t)orow * FDIM + n) = hh;
                        *(__nv_bfloat162*)(g_Hlo + (size_t)orow * FDIM + n) = ll;
                    } else {
                        float2 t; t.x = v0; t.y = v1;
                        *(float2*)(g_Y + (size_t)orow * DDIM + n) = t;
                    }
                }
            }
        }
    }
}

// ============================ LN ============================
__global__ void ln_kernel(const float* __restrict__ tgt,
                          const float* __restrict__ gamma,
                          const float* __restrict__ beta,
                          float* __restrict__ out) {
    int token = blockIdx.x;
    int tid = threadIdx.x;
    __shared__ float red[8];

    float w0 = g_slotw[2 * token], w1 = g_slotw[2 * token + 1];
    const float* x  = tgt + (size_t)token * DDIM;
    const float* y0 = g_Y + (size_t)(2 * token) * DDIM;
    const float* y1 = y0 + DDIM;

    float v[4];
    float s = 0.f;
#pragma unroll
    for (int i = 0; i < 4; i++) {
        int d = tid + 256 * i;
        v[i] = x[d] + w0 * y0[d] + w1 * y1[d];
        s += v[i];
    }
#pragma unroll
    for (int o = 16; o > 0; o >>= 1) s += __shfl_xor_sync(0xffffffffu, s, o);
    if ((tid & 31) == 0) red[tid >> 5] = s;
    __syncthreads();
    float mu = (red[0] + red[1] + red[2] + red[3] + red[4] + red[5] + red[6] + red[7]) * (1.f / DDIM);

    float sq = 0.f;
#pragma unroll
    for (int i = 0; i < 4; i++) { float dv = v[i] - mu; sq += dv * dv; }
#pragma unroll
    for (int o = 16; o > 0; o >>= 1) sq += __shfl_xor_sync(0xffffffffu, sq, o);
    __syncthreads();
    if ((tid & 31) == 0) red[tid >> 5] = sq;
    __syncthreads();
    float var = (red[0] + red[1] + red[2] + red[3] + red[4] + red[5] + red[6] + red[7]) * (1.f / DDIM);
    float inv = rsqrtf(var + LN_EPS);

#pragma unroll
    for (int i = 0; i < 4; i++) {
        int d = tid + 256 * i;
        out[(size_t)token * DDIM + d] = (v[i] - mu) * inv * gamma[d] + beta[d];
    }
}

// ============================ launch ============================
extern "C" void kernel_launch(void* const* d_in, const int* in_sizes, int n_in,
                              void* d_out, int out_size) {
    const float* tgt   = (const float*)d_in[0];
    const float* Wr    = (const float*)d_in[1];
    const float* br    = (const float*)d_in[2];
    const float* W1    = (const float*)d_in[3];
    const float* b1    = (const float*)d_in[4];
    const float* W2    = (const float*)d_in[5];
    const float* b2    = (const float*)d_in[6];
    const float* gamma = (const float*)d_in[7];
    const float* beta  = (const float*)d_in[8];
    float* out = (float*)d_out;

    cudaFuncSetAttribute(mma_gemm_kernel,
                         cudaFuncAttributeMaxDynamicSharedMemorySize, SMEM_BYTES);

    init_counts_kernel<<<1, 32>>>();
    router_kernel<<<N_TOK / 8, 256>>>(tgt, Wr, br);

    // bf16 hi/lo splits
    {
        __nv_bfloat16 *xh, *xl, *w1h, *w1l, *w2h, *w2l;
        cudaGetSymbolAddress((void**)&xh,  g_Xhi);
        cudaGetSymbolAddress((void**)&xl,  g_Xlo);
        cudaGetSymbolAddress((void**)&w1h, g_W1hi);
        cudaGetSymbolAddress((void**)&w1l, g_W1lo);
        cudaGetSymbolAddress((void**)&w2h, g_W2hi);
        cudaGetSymbolAddress((void**)&w2l, g_W2lo);
        int nx = N_TOK * DDIM;              // 4,194,304
        int nw = NEXP * FDIM * DDIM;        // 33,554,432
        split_bf16_kernel<<<nx / 1024, 256>>>(tgt, xh, xl, nx);
        split_bf16_kernel<<<nw / 1024, 256>>>(W1, w1h, w1l, nw);
        split_bf16_kernel<<<nw / 1024, 256>>>(W2, w2h, w2l, nw);
    }

    // GEMM1: [cnt_e,1024] x W1^T -> H (bias+relu, bf16 hi/lo), tensor cores
    dim3 g1(N_TOK / BM, FDIM / BN, NEXP);   // x=mt, y=nt, z=e
    mma_gemm_kernel<<<g1, 512, SMEM_BYTES>>>(1, FDIM, DDIM, b1);

    // GEMM2: [cnt_e,4096] x W2^T -> Y fp32
    dim3 g2(N_TOK / BM, DDIM / BN, NEXP);   // (32, 8, 8)
    mma_gemm_kernel<<<g2, 512, SMEM_BYTES>>>(0, DDIM, FDIM, b2);

    ln_kernel<<<N_TOK, 256>>>(tgt, gamma, beta, out);
}

// round 11
// speedup vs baseline: 2.2919x; 1.0407x over previous
#include <cuda_runtime.h>
#include <cuda_fp16.h>
#include <math.h>
#include <stdint.h>

#define N_TOK 4096      // B*S
#define DDIM  1024      // D
#define FDIM  4096      // F
#define NEXP  8         // E
#define LN_EPS 1e-5f

#define BM 128
#define BN 128
#define BK 32
#define ROWB 80                  // smem bytes per row: 32 fp16 + 8 pad
#define ATILE (128 * ROWB)       // 10240 B per operand tile
#define STAGEB (4 * ATILE)       // Ah, Al, Bh, Bl = 40960 B per stage
#define NSTAGE 3
#define SMEM_BYTES (NSTAGE * STAGEB)  // 122880 B

// ---- static device scratch (no runtime allocation allowed) ----
__device__ int   g_counts[NEXP];
__device__ int   g_rows[NEXP * N_TOK];          // value = token*2 + slot
__device__ float g_slotw[2 * N_TOK];            // softmax weight per slot
__device__ __half g_Xhi[N_TOK * DDIM];
__device__ __half g_Xlo[N_TOK * DDIM];
__device__ __half g_W1hi[NEXP * FDIM * DDIM];
__device__ __half g_W1lo[NEXP * FDIM * DDIM];
__device__ __half g_W2hi[NEXP * DDIM * FDIM];
__device__ __half g_W2lo[NEXP * DDIM * FDIM];
__device__ __half g_Hhi[(size_t)2 * N_TOK * FDIM];
__device__ __half g_Hlo[(size_t)2 * N_TOK * FDIM];
__device__ float g_Y[(size_t)2 * N_TOK * DDIM]; // [8192][1024] H@W2^T+b2 (unweighted)

// ============================ PTX helpers ============================
static __device__ __forceinline__ void cp16(uint32_t s, const void* g) {
    asm volatile("cp.async.cg.shared.global [%0], [%1], 16;" :: "r"(s), "l"(g));
}

#define LDSM4(r0, r1, r2, r3, addr)                                           \
    asm volatile("ldmatrix.sync.aligned.m8n8.x4.shared.b16 {%0,%1,%2,%3}, [%4];" \
                 : "=r"(r0), "=r"(r1), "=r"(r2), "=r"(r3) : "r"(addr))

// fp16 inputs, fp32 accumulators (main term)
#define MMAF32(d, a, b0, b1)                                                  \
    asm volatile("mma.sync.aligned.m16n8k16.row.col.f32.f16.f16.f32 "         \
                 "{%0,%1,%2,%3}, {%4,%5,%6,%7}, {%8,%9}, {%0,%1,%2,%3};"      \
                 : "+f"((d)[0]), "+f"((d)[1]), "+f"((d)[2]), "+f"((d)[3])     \
                 : "r"((a)[0]), "r"((a)[1]), "r"((a)[2]), "r"((a)[3]),        \
                   "r"(b0), "r"(b1))

// fp16 inputs, fp16 accumulators (correction terms)
#define MMAF16(d, a, b0, b1)                                                  \
    asm volatile("mma.sync.aligned.m16n8k16.row.col.f16.f16.f16.f16 "         \
                 "{%0,%1}, {%2,%3,%4,%5}, {%6,%7}, {%0,%1};"                  \
                 : "+r"((d)[0]), "+r"((d)[1])                                 \
                 : "r"((a)[0]), "r"((a)[1]), "r"((a)[2]), "r"((a)[3]),        \
                   "r"(b0), "r"(b1))

// ============================ small kernels ============================
__global__ void init_counts_kernel() {
    if (threadIdx.x < NEXP) g_counts[threadIdx.x] = 0;
}

// fp32 -> fp16 hi/lo split
__global__ void split_fp16_kernel(const float* __restrict__ src,
                                  __half* __restrict__ hi,
                                  __half* __restrict__ lo, int n) {
    int i = (blockIdx.x * blockDim.x + threadIdx.x) * 4;
    if (i >= n) return;
    float4 v = *(const float4*)(src + i);
    float vv[4] = {v.x, v.y, v.z, v.w};
    __half h[4], l[4];
#pragma unroll
    for (int j = 0; j < 4; j++) {
        h[j] = __float2half_rn(vv[j]);
        l[j] = __float2half_rn(vv[j] - __half2float(h[j]));
    }
    __half2 h0; h0.x = h[0]; h0.y = h[1];
    __half2 h1; h1.x = h[2]; h1.y = h[3];
    __half2 l0; l0.x = l[0]; l0.y = l[1];
    __half2 l1; l1.x = l[2]; l1.y = l[3];
    *(__half2*)(hi + i)     = h0;
    *(__half2*)(hi + i + 2) = h1;
    *(__half2*)(lo + i)     = l0;
    *(__half2*)(lo + i + 2) = l1;
}

// One warp per token: 8 logits, top-2, softmax, append to expert lists.
__global__ void router_kernel(const float* __restrict__ tgt,
                              const float* __restrict__ Wr,
                              const float* __restrict__ br) {
    int token = blockIdx.x * 8 + (threadIdx.x >> 5);
    int lane  = threadIdx.x & 31;
    if (token >= N_TOK) return;

    const float* x = tgt + (size_t)token * DDIM;
    float xr[32];
#pragma unroll
    for (int i = 0; i < 32; i++) xr[i] = x[lane + 32 * i];

    float logits[NEXP];
#pragma unroll
    for (int e = 0; e < NEXP; e++) {
        const float* w = Wr + e * DDIM;
        float s = 0.f;
#pragma unroll
        for (int i = 0; i < 32; i++) s += xr[i] * w[lane + 32 * i];
#pragma unroll
        for (int o = 16; o > 0; o >>= 1) s += __shfl_xor_sync(0xffffffffu, s, o);
        logits[e] = s + br[e];
    }

    if (lane == 0) {
        int i0 = 0; float v0 = logits[0];
#pragma unroll
        for (int e = 1; e < NEXP; e++) if (logits[e] > v0) { v0 = logits[e]; i0 = e; }
        int i1 = -1; float v1 = -INFINITY;
#pragma unroll
        for (int e = 0; e < NEXP; e++) if (e != i0 && logits[e] > v1) { v1 = logits[e]; i1 = e; }
        float e1  = expf(v1 - v0);
        float inv = 1.f / (1.f + e1);
        g_slotw[2 * token]     = inv;
        g_slotw[2 * token + 1] = e1 * inv;
        int p0 = atomicAdd(&g_counts[i0], 1); g_rows[i0 * N_TOK + p0] = 2 * token;
        int p1 = atomicAdd(&g_counts[i1], 1); g_rows[i1 * N_TOK + p1] = 2 * token + 1;
    }
}

// ============================ mma.sync grouped GEMM ============================
// C[m][n] = sum_k A[m][k]*B[n][k], A/B each split fp16 hi+lo:
//   accM(fp32) += Ah*Bh ;  accC(fp16) += Ah*Bl + Al*Bh ;  C = accM + accC
// 512 thr = 16 warps (4 M x 4 N), warp tile 32x32, block tile 128x128, BK=32.
// 3-stage cp.async ring, ONE __syncthreads per K-chunk.
__global__ void __launch_bounds__(512, 1)
mma_gemm_kernel(int is_gemm1, int Ndim, int Kdim, const float* __restrict__ bias) {
    extern __shared__ __align__(128) char smem[];
    uint32_t sb = (uint32_t)__cvta_generic_to_shared(smem);

    int e  = blockIdx.z;
    int nt = blockIdx.y;
    int mt = blockIdx.x;     // mt fastest -> concurrent blocks share weight tile (L2)
    int cnt = g_counts[e];
    if (mt * BM >= cnt) return;

    const int* erows = g_rows + e * N_TOK;
    const __half *Ahb, *Alb, *Whb, *Wlb;
    if (is_gemm1) { Ahb = g_Xhi; Alb = g_Xlo; Whb = g_W1hi; Wlb = g_W1lo; }
    else          { Ahb = g_Hhi; Alb = g_Hlo; Whb = g_W2hi; Wlb = g_W2lo; }

    int tid = threadIdx.x;

    // ---- global->smem geometry: thread -> (row = tid>>2, 16B seg = tid&3) ----
    int lrow = tid >> 2;
    int seg  = tid & 3;
    int kb   = seg * 8;                      // element offset of this thread's 16B
    int mr_l = mt * BM + lrow; if (mr_l > cnt - 1) mr_l = cnt - 1;
    int arow = erows[mr_l]; if (is_gemm1) arow >>= 1;
    const __half* aph = Ahb + (size_t)arow * Kdim + kb;
    const __half* apl = Alb + (size_t)arow * Kdim + kb;
    size_t wo = ((size_t)e * Ndim + nt * BN + lrow) * Kdim + kb;
    const __half* bph = Whb + wo;
    const __half* bpl = Wlb + wo;
    uint32_t dst = (uint32_t)lrow * ROWB + seg * 16;

    // ---- fragment (ldmatrix) geometry ----
    int lane = tid & 31, wid = tid >> 5;
    int wm = wid & 3, wn = wid >> 2;         // warp tile origin (wm*32, wn*32)
    uint32_t afa = (uint32_t)(wm * 32 + (lane & 15)) * ROWB + (lane >> 4) * 16;
    uint32_t bfa = (uint32_t)(wn * 32 + (lane & 15)) * ROWB + (lane >> 4) * 16;

    float    accM[2][4][4];
    uint32_t accC[2][4][2];
#pragma unroll
    for (int mi = 0; mi < 2; mi++)
#pragma unroll
        for (int ni = 0; ni < 4; ni++) {
#pragma unroll
            for (int r = 0; r < 4; r++) accM[mi][ni][r] = 0.f;
            accC[mi][ni][0] = 0u; accC[mi][ni][1] = 0u;
        }

    auto issue = [&](int i) {
        uint32_t d = sb + (uint32_t)(i % NSTAGE) * STAGEB + dst;
        size_t ko = (size_t)i * BK;
        cp16(d,              aph + ko);
        cp16(d + ATILE,      apl + ko);
        cp16(d + 2 * ATILE,  bph + ko);
        cp16(d + 3 * ATILE,  bpl + ko);
        asm volatile("cp.async.commit_group;" ::: "memory");
    };

    int nch = Kdim / BK;
    issue(0);
    if (nch > 1) issue(1);
    for (int i = 0; i < nch; i++) {
        if (i + 1 < nch) {
            asm volatile("cp.async.wait_group 1;" ::: "memory");
        } else {
            asm volatile("cp.async.wait_group 0;" ::: "memory");
        }
        __syncthreads();   // chunk i visible; stage (i+2)%3 free for reuse
        if (i + 2 < nch) issue(i + 2);

        uint32_t bb = sb + (uint32_t)(i % NSTAGE) * STAGEB;
#pragma unroll
        for (int s = 0; s < 2; s++) {        // two k16 steps per chunk
            uint32_t aA = bb + afa + s * 32;             // Ah (then Al)
            uint32_t aB = bb + 2 * ATILE + bfa + s * 32; // Bh
            uint32_t af[2][4], bhf[2][4], blf[2][4];

            // Ah fragments (2) + Bh fragments (2)
#pragma unroll
            for (int mi = 0; mi < 2; mi++)
                LDSM4(af[mi][0], af[mi][1], af[mi][2], af[mi][3], aA + mi * 16 * ROWB);
#pragma unroll
            for (int nj = 0; nj < 2; nj++)
                LDSM4(bhf[nj][0], bhf[nj][1], bhf[nj][2], bhf[nj][3], aB + nj * 16 * ROWB);

            // main: Ah * Bh -> fp32 accum
#pragma unroll
            for (int mi = 0; mi < 2; mi++)
#pragma unroll
                for (int ni = 0; ni < 4; ni++)
                    MMAF32(accM[mi][ni], af[mi],
                           bhf[ni >> 1][ni & 1], bhf[ni >> 1][(ni & 1) + 2]);

            // Bl fragments (2)
#pragma unroll
            for (int nj = 0; nj < 2; nj++)
                LDSM4(blf[nj][0], blf[nj][1], blf[nj][2], blf[nj][3],
                      aB + ATILE + nj * 16 * ROWB);

            // corr: Ah * Bl -> fp16 accum
#pragma unroll
            for (int mi = 0; mi < 2; mi++)
#pragma unroll
                for (int ni = 0; ni < 4; ni++)
                    MMAF16(accC[mi][ni], af[mi],
                           blf[ni >> 1][ni & 1], blf[ni >> 1][(ni & 1) + 2]);

            // Al fragments overwrite Ah slots (2)
#pragma unroll
            for (int mi = 0; mi < 2; mi++)
                LDSM4(af[mi][0], af[mi][1], af[mi][2], af[mi][3],
                      aA + ATILE + mi * 16 * ROWB);

            // corr: Al * Bh -> fp16 accum
#pragma unroll
            for (int mi = 0; mi < 2; mi++)
#pragma unroll
                for (int ni = 0; ni < 4; ni++)
                    MMAF16(accC[mi][ni], af[mi],
                           bhf[ni >> 1][ni & 1], bhf[ni >> 1][(ni & 1) + 2]);
        }
    }

    // ---- epilogue ----
    int tg = lane >> 2, tc = (lane & 3) * 2;
    const float* bbias = bias + e * Ndim + nt * BN;
    float bias_r[8];
#pragma unroll
    for (int ni = 0; ni < 4; ni++) {
        int c = wn * 32 + ni * 8 + tc;
        bias_r[2 * ni]     = __ldg(bbias + c);
        bias_r[2 * ni + 1] = __ldg(bbias + c + 1);
    }
#pragma unroll
    for (int mi = 0; mi < 2; mi++) {
#pragma unroll
        for (int half = 0; half < 2; half++) {
            int r = wm * 32 + mi * 16 + tg + half * 8;
            int mr = mt * BM + r;
            if (mr < cnt) {
                int orow = erows[mr];
#pragma unroll
                for (int ni = 0; ni < 4; ni++) {
                    int c = wn * 32 + ni * 8 + tc;
                    __half2 hc = *reinterpret_cast<__half2*>(&accC[mi][ni][half]);
                    float v0 = accM[mi][ni][half * 2]     + __low2float(hc)  + bias_r[2 * ni];
                    float v1 = accM[mi][ni][half * 2 + 1] + __high2float(hc) + bias_r[2 * ni + 1];
                    int n = nt * BN + c;
                    if (is_gemm1) {
                        v0 = fmaxf(v0, 0.f); v1 = fmaxf(v1, 0.f);
                        __half h0 = __float2half_rn(v0);
                        __half h1 = __float2half_rn(v1);
                        __half2 hh; hh.x = h0; hh.y = h1;
                        __half2 ll;
                        ll.x = __float2half_rn(v0 - __half2float(h0));
                        ll.y = __float2half_rn(v1 - __half2float(h1));
                        *(__half2*)(g_Hhi + (size_t)orow * FDIM + n) = hh;
                        *(__half2*)(g_Hlo + (size_t)orow * FDIM + n) = ll;
                    } else {
                        float2 t; t.x = v0; t.y = v1;
                        *(float2*)(g_Y + (size_t)orow * DDIM + n) = t;
                    }
                }
            }
        }
    }
}

// ============================ LN ============================
__global__ void ln_kernel(const float* __restrict__ tgt,
                          const float* __restrict__ gamma,
                          const float* __restrict__ beta,
                          float* __restrict__ out) {
    int token = blockIdx.x;
    int tid = threadIdx.x;
    __shared__ float red[8];

    float w0 = g_slotw[2 * token], w1 = g_slotw[2 * token + 1];
    const float* x  = tgt + (size_t)token * DDIM;
    const float* y0 = g_Y + (size_t)(2 * token) * DDIM;
    const float* y1 = y0 + DDIM;

    float v[4];
    float s = 0.f;
#pragma unroll
    for (int i = 0; i < 4; i++) {
        int d = tid + 256 * i;
        v[i] = x[d] + w0 * y0[d] + w1 * y1[d];
        s += v[i];
    }
#pragma unroll
    for (int o = 16; o > 0; o >>= 1) s += __shfl_xor_sync(0xffffffffu, s, o);
    if ((tid & 31) == 0) red[tid >> 5] = s;
    __syncthreads();
    float mu = (red[0] + red[1] + red[2] + red[3] + red[4] + red[5] + red[6] + red[7]) * (1.f / DDIM);

    float sq = 0.f;
#pragma unroll
    for (int i = 0; i < 4; i++) { float dv = v[i] - mu; sq += dv * dv; }
#pragma unroll
    for (int o = 16; o > 0; o >>= 1) sq += __shfl_xor_sync(0xffffffffu, sq, o);
    __syncthreads();
    if ((tid & 31) == 0) red[tid >> 5] = sq;
    __syncthreads();
    float var = (red[0] + red[1] + red[2] + red[3] + red[4] + red[5] + red[6] + red[7]) * (1.f / DDIM);
    float inv = rsqrtf(var + LN_EPS);

#pragma unroll
    for (int i = 0; i < 4; i++) {
        int d = tid + 256 * i;
        out[(size_t)token * DDIM + d] = (v[i] - mu) * inv * gamma[d] + beta[d];
    }
}

// ============================ launch ============================
extern "C" void kernel_launch(void* const* d_in, const int* in_sizes, int n_in,
                              void* d_out, int out_size) {
    const float* tgt   = (const float*)d_in[0];
    const float* Wr    = (const float*)d_in[1];
    const float* br    = (const float*)d_in[2];
    const float* W1    = (const float*)d_in[3];
    const float* b1    = (const float*)d_in[4];
    const float* W2    = (const float*)d_in[5];
    const float* b2    = (const float*)d_in[6];
    const float* gamma = (const float*)d_in[7];
    const float* beta  = (const float*)d_in[8];
    float* out = (float*)d_out;

    cudaFuncSetAttribute(mma_gemm_kernel,
                         cudaFuncAttributeMaxDynamicSharedMemorySize, SMEM_BYTES);

    init_counts_kernel<<<1, 32>>>();
    router_kernel<<<N_TOK / 8, 256>>>(tgt, Wr, br);

    // fp16 hi/lo splits
    {
        __half *xh, *xl, *w1h, *w1l, *w2h, *w2l;
        cudaGetSymbolAddress((void**)&xh,  g_Xhi);
        cudaGetSymbolAddress((void**)&xl,  g_Xlo);
        cudaGetSymbolAddress((void**)&w1h, g_W1hi);
        cudaGetSymbolAddress((void**)&w1l, g_W1lo);
        cudaGetSymbolAddress((void**)&w2h, g_W2hi);
        cudaGetSymbolAddress((void**)&w2l, g_W2lo);
        int nx = N_TOK * DDIM;              // 4,194,304
        int nw = NEXP * FDIM * DDIM;        // 33,554,432
        split_fp16_kernel<<<nx / 1024, 256>>>(tgt, xh, xl, nx);
        split_fp16_kernel<<<nw / 1024, 256>>>(W1, w1h, w1l, nw);
        split_fp16_kernel<<<nw / 1024, 256>>>(W2, w2h, w2l, nw);
    }

    // GEMM1: [cnt_e,1024] x W1^T -> H (bias+relu, fp16 hi/lo), tensor cores
    dim3 g1(N_TOK / BM, FDIM / BN, NEXP);   // x=mt, y=nt, z=e
    mma_gemm_kernel<<<g1, 512, SMEM_BYTES>>>(1, FDIM, DDIM, b1);

    // GEMM2: [cnt_e,4096] x W2^T -> Y fp32
    dim3 g2(N_TOK / BM, DDIM / BN, NEXP);   // (32, 8, 8)
    mma_gemm_kernel<<<g2, 512, SMEM_BYTES>>>(0, DDIM, FDIM, b2);

    ln_kernel<<<N_TOK, 256>>>(tgt, gamma, beta, out);
}